// round 3
// baseline (speedup 1.0000x reference)
#include <cuda_runtime.h>

#define B_DIM 256
#define N_DIM 256
#define EPS_F 1e-7f
#define TAU   0.1f        // series/exact threshold on x = e_k/den_i
#define CAND_MAX 256

// Scratch (no allocations allowed anywhere)
__device__ int          g_partial[32];
__device__ float2       g_tf[B_DIM];
__device__ unsigned int g_ticket;

// -----------------------------------------------------------------------------
// valid_mask dtype detection (32 blocks). bit0: all words <=1 (int32 0/1);
// bit1: all words in {0, 1.0f} (float32). Bool byte-packed fails both.
// -----------------------------------------------------------------------------
__global__ void __launch_bounds__(256) detect_mask_kernel(const unsigned int* __restrict__ m) {
    const unsigned int idx = blockIdx.x * 512u + threadIdx.x * 2u;
    const uint2 u = *reinterpret_cast<const uint2*>(m + idx);
    bool ok01 = (u.x <= 1u) && (u.y <= 1u);
    bool okf  = (u.x == 0u || u.x == 0x3f800000u) && (u.y == 0u || u.y == 0x3f800000u);
    ok01 = __syncthreads_and(ok01);
    okf  = __syncthreads_and(okf);
    if (threadIdx.x == 0)
        g_partial[blockIdx.x] = (ok01 ? 1 : 0) | (okf ? 2 : 0);
}

__device__ __forceinline__ float poly_mlog1m(float x) {
    // Sum_{m=1..4} x^m/m  (approximates -log(1-x))
    return x * fmaf(x, fmaf(x, fmaf(x, 0.25f, 1.0f / 3.0f), 0.5f), 1.0f);
}

// -----------------------------------------------------------------------------
// One block per batch row. Sort by tm desc, prefix-sum powers of e, then
//   part2_i = Sum_m S_m(cnt_i)/(m den_i^m)  - poly(x_self)  + exact corrections
// for the few pairs with x > TAU (candidate list: e_k > TAU * sden[k] is a
// superset since den_i >= sden[k] for every pair (i,k) with k < cnt_i).
// -----------------------------------------------------------------------------
__global__ void __launch_bounds__(N_DIM) cox_kernel(
    const float* __restrict__ pred,
    const float* __restrict__ target,
    const void*  __restrict__ mask_raw,
    float* __restrict__ out)
{
    const int b = blockIdx.x;
    const int i = threadIdx.x;
    const int base = b * N_DIM;
    const int lane = i & 31, wid = i >> 5;

    __shared__ float  a_tm[N_DIM];
    __shared__ float  stm[N_DIM];
    __shared__ float  se [N_DIM];
    __shared__ float  sp [N_DIM];
    __shared__ float4 spow[N_DIM];     // inclusive prefix sums of (e, e^2, e^3, e^4)
    __shared__ float4 swsum4[8];
    __shared__ float  sred[8];
    __shared__ float  sred2[8];
    __shared__ int    warp_cc[8];
    __shared__ float  cand_e[CAND_MAX];
    __shared__ int    cand_k[CAND_MAX];
    __shared__ int    s_mode;
    __shared__ int    s_islast;

    // Issue independent loads first
    const float p  = pred[base + i];
    const float t  = target[base + i];
    const unsigned int   mw = ((const unsigned int*)mask_raw)[base + i];
    const unsigned char  mb = ((const unsigned char*)mask_raw)[base + i];

    // Aggregate dtype mode (word modes int/float both test word != 0)
    if (i < 32) {
        int f = __reduce_and_sync(0xffffffffu, g_partial[i]);
        if (i == 0) s_mode = (f & 3) ? 1 : 0;
    }
    __syncthreads();

    const bool v = s_mode ? (mw != 0u) : (mb != 0);
    const float tm = v ? t : -1.0f;
    const float e  = __expf(p);
    a_tm[i] = tm;
    __syncthreads();

    // Rank (descending tm, ties by index) — float4 over shared
    int rank = 0;
    const float4* tm4 = reinterpret_cast<const float4*>(a_tm);
    #pragma unroll 8
    for (int g = 0; g < N_DIM / 4; ++g) {
        const float4 q = tm4[g];
        const int j = g * 4;
        rank += (int)((q.x > tm) || ((q.x == tm) && (j     < i)));
        rank += (int)((q.y > tm) || ((q.y == tm) && (j + 1 < i)));
        rank += (int)((q.z > tm) || ((q.z == tm) && (j + 2 < i)));
        rank += (int)((q.w > tm) || ((q.w == tm) && (j + 3 < i)));
    }
    stm[rank] = tm;
    se [rank] = e;
    sp [rank] = p;
    __syncthreads();

    // Inclusive prefix scan of (e, e^2, e^3, e^4) in sorted order
    {
        const float es = se[i];
        const float e2 = es * es;
        float4 x = make_float4(es, e2, e2 * es, e2 * e2);
        #pragma unroll
        for (int o = 1; o < 32; o <<= 1) {
            const float t0 = __shfl_up_sync(0xffffffffu, x.x, o);
            const float t1 = __shfl_up_sync(0xffffffffu, x.y, o);
            const float t2 = __shfl_up_sync(0xffffffffu, x.z, o);
            const float t3 = __shfl_up_sync(0xffffffffu, x.w, o);
            if (lane >= o) { x.x += t0; x.y += t1; x.z += t2; x.w += t3; }
        }
        if (lane == 31) swsum4[wid] = x;
        __syncthreads();
        if (i < 8) {
            float4 w = swsum4[i];
            #pragma unroll
            for (int o = 1; o < 8; o <<= 1) {
                const float t0 = __shfl_up_sync(0x000000ffu, w.x, o);
                const float t1 = __shfl_up_sync(0x000000ffu, w.y, o);
                const float t2 = __shfl_up_sync(0x000000ffu, w.z, o);
                const float t3 = __shfl_up_sync(0x000000ffu, w.w, o);
                if (i >= o) { w.x += t0; w.y += t1; w.z += t2; w.w += t3; }
            }
            swsum4[i] = w;
        }
        __syncthreads();
        if (wid > 0) {
            const float4 o4 = swsum4[wid - 1];
            x.x += o4.x; x.y += o4.y; x.z += o4.z; x.w += o4.w;
        }
        spow[i] = x;
    }
    __syncthreads();

    // Candidate compaction: slots k with e_k > TAU * sden[k] (k-ascending)
    {
        const bool flag = (se[i] > TAU * spow[i].x);
        const unsigned int bal = __ballot_sync(0xffffffffu, flag);
        if (lane == 0) warp_cc[wid] = __popc(bal);
        __syncthreads();
        int off = 0;
        #pragma unroll
        for (int w = 0; w < 8; ++w) off += (w < wid) ? warp_cc[w] : 0;
        if (flag) {
            const int pos = off + __popc(bal & ((1u << lane) - 1u));
            cand_e[pos] = se[i];
            cand_k[pos] = i;
        }
    }
    __syncthreads();
    int Q = 0;
    #pragma unroll
    for (int w = 0; w < 8; ++w) Q += warp_cc[w];

    // Per-slot compute (thread i owns sorted slot i)
    const float tm_s = stm[i];
    const float bmax = stm[0];
    float contrib = 0.0f;
    const bool elim = (tm_s > 0.0f) && (tm_s < bmax);
    if (elim) {
        // cnt = largest prefix with stm[prefix-1] >= tm_s (ties included)
        int cnt = 0;
        #pragma unroll
        for (int step = 128; step > 0; step >>= 1) {
            const int probe = cnt + step;
            if (stm[probe - 1] >= tm_s) cnt = probe;
        }
        const float4 S  = spow[cnt - 1];
        const float den = S.x;
        const float id  = __fdividef(1.0f, den);
        const float id2 = id * id;
        float part2 = S.x * id + 0.5f * (S.y * id2)
                    + (1.0f / 3.0f) * (S.z * (id2 * id)) + 0.25f * (S.w * (id2 * id2));
        part2 -= poly_mlog1m(se[i] * id);   // remove self term exactly

        // Exact-log corrections for the few large-x pairs
        for (int q = 0; q < Q; ++q) {
            const int k = cand_k[q];
            if (k >= cnt) break;            // list ascending in k
            const float x = cand_e[q] * id;
            if (x > TAU && k != i) {
                const float ex = -__logf(fmaxf(1.0f + EPS_F - x, 2.0f * EPS_F));
                contrib += ex - poly_mlog1m(x);
            }
        }
        const float w = fminf(fmaxf((bmax - tm_s) / fmaxf(bmax, 1.0f), 0.0f), 1.0f);
        contrib = (__logf(den) - sp[i] + part2 + contrib) * w;
    }

    // Block reduce contribs
    #pragma unroll
    for (int o = 16; o > 0; o >>= 1)
        contrib += __shfl_xor_sync(0xffffffffu, contrib, o);
    if (lane == 0) sred[wid] = contrib;
    __syncthreads();
    if (i == 0) {
        float s = 0.0f;
        #pragma unroll
        for (int k = 0; k < 8; ++k) s += sred[k];
        const float flag = (stm[1] >= 0.0f) ? 1.0f : 0.0f;   // >=2 valid
        g_tf[b] = make_float2(s * flag, flag);
        __threadfence();
        const unsigned int tk = atomicAdd(&g_ticket, 1u);
        s_islast = (tk == gridDim.x - 1) ? 1 : 0;
    }
    __syncthreads();

    // Last finishing block: deterministic final reduction
    if (s_islast) {
        if (i == 0) g_ticket = 0;
        __threadfence();
        const float2 tf = g_tf[i];
        float T = tf.x, F = tf.y;
        #pragma unroll
        for (int o = 16; o > 0; o >>= 1) {
            T += __shfl_xor_sync(0xffffffffu, T, o);
            F += __shfl_xor_sync(0xffffffffu, F, o);
        }
        if (lane == 0) { sred[wid] = T; sred2[wid] = F; }
        __syncthreads();
        if (i == 0) {
            float TT = 0.0f, FF = 0.0f;
            #pragma unroll
            for (int k = 0; k < 8; ++k) { TT += sred[k]; FF += sred2[k]; }
            out[0] = TT / fmaxf(FF, 1.0f);
        }
    }
}

extern "C" void kernel_launch(void* const* d_in, const int* in_sizes, int n_in,
                              void* d_out, int out_size) {
    (void)in_sizes; (void)n_in; (void)out_size;
    const float* pred   = (const float*)d_in[0];
    const float* target = (const float*)d_in[1];
    const void*  mask   = d_in[2];

    detect_mask_kernel<<<32, 256>>>((const unsigned int*)mask);
    cox_kernel<<<B_DIM, N_DIM>>>(pred, target, mask, (float*)d_out);
}

// round 5
// speedup vs baseline: 1.3145x; 1.3145x over previous
#include <cuda_runtime.h>

#define B_DIM 256
#define N_DIM 256
#define EPS_F 1e-7f
#define TAU   0.1f
#define CAND_MAX 256

// Scratch (no allocations allowed anywhere)
__device__ float2       g_tf[B_DIM];
__device__ unsigned int g_ticket;

__device__ __forceinline__ float poly_mlog1m(float x) {
    // Sum_{m=1..4} x^m/m  (approximates -log(1-x))
    return x * fmaf(x, fmaf(x, fmaf(x, 0.25f, 1.0f / 3.0f), 0.5f), 1.0f);
}

// -----------------------------------------------------------------------------
// One block per batch row b.
//  * unique 64-bit sort key: (ordered_uint(tm) << 32) | i
//  * warp bitonic sort (ascending, in-register, shfl) -> 8 sorted runs of 32
//  * global rank = sum over runs of count(key' < key): 5-probe binary search
//    over the first 31 elements + 1 branch-free probe for the 32nd (the
//    missing probe was the round-4 bug: whole-run-less cases undercounted)
//  * scatter (tm, e, p) into descending-tm order; prefix-scan powers of e
//  * part2 via 4-term log series on prefix sums + exact corrections for the
//    few pairs with e_k/den > TAU (superset test e_k > TAU*prefix_e[k])
//  * last finishing block does the deterministic final reduction
// -----------------------------------------------------------------------------
__global__ void __launch_bounds__(N_DIM) cox_kernel(
    const float* __restrict__ pred,
    const float* __restrict__ target,
    const unsigned int* __restrict__ mask,
    float* __restrict__ out)
{
    const int b = blockIdx.x;
    const int i = threadIdx.x;
    const int base = b * N_DIM;
    const int lane = i & 31, wid = i >> 5;

    __shared__ float  a_tm[N_DIM], a_e[N_DIM], a_p[N_DIM];   // original order
    __shared__ unsigned long long skey[N_DIM];                // 8 sorted runs
    __shared__ float  stm[N_DIM], se[N_DIM], sp[N_DIM];       // sorted (desc tm)
    __shared__ float4 spow[N_DIM];                            // prefix sums e^1..e^4
    __shared__ float4 swsum4[8];
    __shared__ float  sred[8], sred2[8];
    __shared__ int    warp_cc[8];
    __shared__ float  cand_e[CAND_MAX];
    __shared__ int    cand_k[CAND_MAX];
    __shared__ int    s_islast;

    // Loads (mask elements are 4-byte; !=0 covers int and float encodings)
    const float p  = pred[base + i];
    const float t  = target[base + i];
    const bool  v  = mask[base + i] != 0u;

    const float tm = v ? t : -1.0f;
    const float e  = __expf(p);
    a_tm[i] = tm; a_e[i] = e; a_p[i] = p;

    // Unique 64-bit key: high = order-preserving uint of tm, low = index
    const unsigned int fb = __float_as_uint(tm);
    const unsigned int u  = fb ^ ((fb & 0x80000000u) ? 0xFFFFFFFFu : 0x80000000u);
    unsigned long long key = ((unsigned long long)u << 32) | (unsigned int)i;

    // Warp bitonic sort, ascending across lanes (15 compare-exchange stages)
    #pragma unroll
    for (int k = 2; k <= 32; k <<= 1) {
        #pragma unroll
        for (int j = k >> 1; j > 0; j >>= 1) {
            const unsigned long long other = __shfl_xor_sync(0xffffffffu, key, j);
            const bool keepmin = (((lane & j) == 0) == ((lane & k) == 0));
            const bool gt = key > other;
            key = (gt == keepmin) ? other : key;
        }
    }
    skey[i] = key;          // run w occupies [32w, 32w+32), ascending
    __syncthreads();

    // Global rank: count keys < mine across all 8 runs.
    int less = 0;
    #pragma unroll
    for (int w = 0; w < 8; ++w) {
        const int rb = w * 32;
        int lo = 0;
        #pragma unroll
        for (int s = 16; s; s >>= 1)
            if (skey[rb + lo + s - 1] < key) lo += s;
        lo += (int)(skey[rb + lo] < key);   // resolve 31 vs 32 (round-4 fix)
        less += lo;
    }
    const int slot = (N_DIM - 1) - less;              // descending-tm slot
    const unsigned int idx = (unsigned int)key;       // original index
    stm[slot] = a_tm[idx];
    se [slot] = a_e[idx];
    sp [slot] = a_p[idx];
    __syncthreads();

    // Inclusive prefix scan of (e, e^2, e^3, e^4) in sorted order
    {
        const float es = se[i];
        const float e2 = es * es;
        float4 x = make_float4(es, e2, e2 * es, e2 * e2);
        #pragma unroll
        for (int o = 1; o < 32; o <<= 1) {
            const float t0 = __shfl_up_sync(0xffffffffu, x.x, o);
            const float t1 = __shfl_up_sync(0xffffffffu, x.y, o);
            const float t2 = __shfl_up_sync(0xffffffffu, x.z, o);
            const float t3 = __shfl_up_sync(0xffffffffu, x.w, o);
            if (lane >= o) { x.x += t0; x.y += t1; x.z += t2; x.w += t3; }
        }
        if (lane == 31) swsum4[wid] = x;
        __syncthreads();
        if (i < 8) {
            float4 w = swsum4[i];
            #pragma unroll
            for (int o = 1; o < 8; o <<= 1) {
                const float t0 = __shfl_up_sync(0x000000ffu, w.x, o);
                const float t1 = __shfl_up_sync(0x000000ffu, w.y, o);
                const float t2 = __shfl_up_sync(0x000000ffu, w.z, o);
                const float t3 = __shfl_up_sync(0x000000ffu, w.w, o);
                if (i >= o) { w.x += t0; w.y += t1; w.z += t2; w.w += t3; }
            }
            swsum4[i] = w;
        }
        __syncthreads();
        if (wid > 0) {
            const float4 o4 = swsum4[wid - 1];
            x.x += o4.x; x.y += o4.y; x.z += o4.z; x.w += o4.w;
        }
        spow[i] = x;
    }
    __syncthreads();

    // Candidate compaction: slots k with e_k > TAU * prefix_e[k] (ascending k)
    {
        const bool flag = (se[i] > TAU * spow[i].x);
        const unsigned int bal = __ballot_sync(0xffffffffu, flag);
        if (lane == 0) warp_cc[wid] = __popc(bal);
        __syncthreads();
        int off = 0;
        #pragma unroll
        for (int w = 0; w < 8; ++w) off += (w < wid) ? warp_cc[w] : 0;
        if (flag) {
            const int pos = off + __popc(bal & ((1u << lane) - 1u));
            cand_e[pos] = se[i];
            cand_k[pos] = i;
        }
    }
    __syncthreads();
    int Q = 0;
    #pragma unroll
    for (int w = 0; w < 8; ++w) Q += warp_cc[w];

    // Per-slot compute (thread i owns sorted slot i)
    const float tm_s = stm[i];
    const float bmax = stm[0];
    float contrib = 0.0f;
    const bool elim = (tm_s > 0.0f) && (tm_s < bmax);
    if (elim) {
        // cnt = largest prefix with stm[prefix-1] >= tm_s (ties included)
        int cnt = 0;
        #pragma unroll
        for (int step = 128; step > 0; step >>= 1) {
            const int probe = cnt + step;
            if (stm[probe - 1] >= tm_s) cnt = probe;
        }
        const float4 S  = spow[cnt - 1];
        const float den = S.x;
        const float id  = __fdividef(1.0f, den);
        const float id2 = id * id;
        float part2 = S.x * id + 0.5f * (S.y * id2)
                    + (1.0f / 3.0f) * (S.z * (id2 * id)) + 0.25f * (S.w * (id2 * id2));
        part2 -= poly_mlog1m(se[i] * id);   // remove self term exactly

        // Exact-log corrections for the few large-x pairs
        for (int q = 0; q < Q; ++q) {
            const int k = cand_k[q];
            if (k >= cnt) break;            // list ascending in k
            const float x = cand_e[q] * id;
            if (x > TAU && k != i) {
                const float ex = -__logf(fmaxf(1.0f + EPS_F - x, 2.0f * EPS_F));
                contrib += ex - poly_mlog1m(x);
            }
        }
        const float w = fminf(fmaxf((bmax - tm_s) / fmaxf(bmax, 1.0f), 0.0f), 1.0f);
        contrib = (__logf(den) - sp[i] + part2 + contrib) * w;
    }

    // Block reduce contribs
    #pragma unroll
    for (int o = 16; o > 0; o >>= 1)
        contrib += __shfl_xor_sync(0xffffffffu, contrib, o);
    if (lane == 0) sred[wid] = contrib;
    __syncthreads();
    if (i == 0) {
        float s = 0.0f;
        #pragma unroll
        for (int k = 0; k < 8; ++k) s += sred[k];
        const float flag = (stm[1] >= 0.0f) ? 1.0f : 0.0f;   // >=2 valid
        g_tf[b] = make_float2(s * flag, flag);
        __threadfence();
        const unsigned int tk = atomicAdd(&g_ticket, 1u);
        s_islast = (tk == gridDim.x - 1) ? 1 : 0;
    }
    __syncthreads();

    // Last finishing block: deterministic final reduction (fixed order)
    if (s_islast) {
        if (i == 0) g_ticket = 0;   // reset for next graph replay
        __threadfence();
        const float2 tf = g_tf[i];
        float T = tf.x, F = tf.y;
        #pragma unroll
        for (int o = 16; o > 0; o >>= 1) {
            T += __shfl_xor_sync(0xffffffffu, T, o);
            F += __shfl_xor_sync(0xffffffffu, F, o);
        }
        if (lane == 0) { sred[wid] = T; sred2[wid] = F; }
        __syncthreads();
        if (i == 0) {
            float TT = 0.0f, FF = 0.0f;
            #pragma unroll
            for (int k = 0; k < 8; ++k) { TT += sred[k]; FF += sred2[k]; }
            out[0] = TT / fmaxf(FF, 1.0f);
        }
    }
}

extern "C" void kernel_launch(void* const* d_in, const int* in_sizes, int n_in,
                              void* d_out, int out_size) {
    (void)in_sizes; (void)n_in; (void)out_size;
    const float*        pred   = (const float*)d_in[0];
    const float*        target = (const float*)d_in[1];
    const unsigned int* mask   = (const unsigned int*)d_in[2];

    cox_kernel<<<B_DIM, N_DIM>>>(pred, target, mask, (float*)d_out);
}

// round 6
// speedup vs baseline: 1.3375x; 1.0175x over previous
#include <cuda_runtime.h>

#define B_DIM 256
#define N_DIM 256
#define EPS_F 1e-7f
#define TAU   0.1f

// Scratch (no allocations allowed anywhere)
__device__ float2       g_tf[B_DIM];
__device__ unsigned int g_ticket;

__device__ __forceinline__ float poly_mlog1m(float x) {
    // Sum_{m=1..4} x^m/m  (approximates -log(1-x))
    return x * fmaf(x, fmaf(x, fmaf(x, 0.25f, 1.0f / 3.0f), 0.5f), 1.0f);
}

// -----------------------------------------------------------------------------
// TWO batch rows per block (512 threads, halves of 256). Per half:
//  * unique 64-bit key (ordered tm bits, index low); warp bitonic sort ->
//    8 ascending runs in shared
//  * rank of the ORIGINAL key via per-run binary search (+1 overflow probe);
//    thread scatters its own (tm,e,p) straight to its descending slot
//  * prefix-scan (e, e^2, e^3, e^4); part2 = 4-term log series on prefix sums
//    - self term + exact-log corrections for pairs with e_k/den > TAU
//  * cnt (risk-set size incl. ties) = slot+1 + walk over equal values
// Last finishing block does the deterministic final reduction.
// -----------------------------------------------------------------------------
__global__ void __launch_bounds__(512) cox_kernel(
    const float* __restrict__ pred,
    const float* __restrict__ target,
    const unsigned int* __restrict__ mask,
    float* __restrict__ out)
{
    const int tid  = threadIdx.x;
    const int hid  = tid >> 8;          // half (row within block)
    const int ti   = tid & 255;         // index within row
    const int lane = tid & 31;
    const int widg = tid >> 5;          // 0..15
    const int w8   = widg & 7;          // warp within half
    const int hb   = hid << 8;          // half base (flat shared offset)
    const int row  = blockIdx.x * 2 + hid;
    const int base = row * N_DIM;

    __shared__ unsigned long long skey[2 * N_DIM];
    __shared__ float  stm[2 * N_DIM], se[2 * N_DIM], sp[2 * N_DIM];
    __shared__ float4 spow[2 * N_DIM];
    __shared__ float4 swsum4[16];
    __shared__ float  sredA[16], sredB[16];
    __shared__ int    warp_cc[16];
    __shared__ float  cand_e[2 * N_DIM];
    __shared__ int    cand_k[2 * N_DIM];
    __shared__ int    s_islast;

    // Loads (mask elements are 4-byte; !=0 covers int and float encodings)
    const float p  = pred[base + ti];
    const float t  = target[base + ti];
    const bool  v  = mask[base + ti] != 0u;

    const float tm = v ? t : -1.0f;
    const float e  = __expf(p);

    // Unique key within the half: high = order-preserving uint of tm, low = ti
    const unsigned int fb = __float_as_uint(tm);
    const unsigned int u  = fb ^ ((fb & 0x80000000u) ? 0xFFFFFFFFu : 0x80000000u);
    const unsigned long long okey = ((unsigned long long)u << 32) | (unsigned int)ti;

    // Warp bitonic sort (ascending across lanes)
    unsigned long long key = okey;
    #pragma unroll
    for (int k = 2; k <= 32; k <<= 1) {
        #pragma unroll
        for (int j = k >> 1; j > 0; j >>= 1) {
            const unsigned long long other = __shfl_xor_sync(0xffffffffu, key, j);
            const bool keepmin = (((lane & j) == 0) == ((lane & k) == 0));
            const bool gt = key > other;
            key = (gt == keepmin) ? other : key;
        }
    }
    skey[tid] = key;            // run w8 of half hid at [hb + w8*32, +32)
    __syncthreads();

    // Rank of the ORIGINAL key across this half's 8 runs; scatter own data.
    int less = 0;
    #pragma unroll
    for (int w = 0; w < 8; ++w) {
        const int rb = hb + w * 32;
        int lo = 0;
        #pragma unroll
        for (int s = 16; s; s >>= 1)
            if (skey[rb + lo + s - 1] < okey) lo += s;
        lo += (int)(skey[rb + lo] < okey);   // resolve 31 vs 32
        less += lo;
    }
    const int slot = (N_DIM - 1) - less;     // descending-tm slot
    stm[hb + slot] = tm;
    se [hb + slot] = e;
    sp [hb + slot] = p;
    __syncthreads();

    // Inclusive prefix scan of (e, e^2, e^3, e^4) in sorted order
    {
        const float es = se[tid];
        const float e2 = es * es;
        float4 x = make_float4(es, e2, e2 * es, e2 * e2);
        #pragma unroll
        for (int o = 1; o < 32; o <<= 1) {
            const float t0 = __shfl_up_sync(0xffffffffu, x.x, o);
            const float t1 = __shfl_up_sync(0xffffffffu, x.y, o);
            const float t2 = __shfl_up_sync(0xffffffffu, x.z, o);
            const float t3 = __shfl_up_sync(0xffffffffu, x.w, o);
            if (lane >= o) { x.x += t0; x.y += t1; x.z += t2; x.w += t3; }
        }
        if (lane == 31) swsum4[widg] = x;
        __syncthreads();
        if (ti < 8) {   // lanes 0..7 of warp 0 (half 0) and warp 8 (half 1)
            float4 w = swsum4[hid * 8 + ti];
            #pragma unroll
            for (int o = 1; o < 8; o <<= 1) {
                const float t0 = __shfl_up_sync(0x000000ffu, w.x, o);
                const float t1 = __shfl_up_sync(0x000000ffu, w.y, o);
                const float t2 = __shfl_up_sync(0x000000ffu, w.z, o);
                const float t3 = __shfl_up_sync(0x000000ffu, w.w, o);
                if (ti >= o) { w.x += t0; w.y += t1; w.z += t2; w.w += t3; }
            }
            swsum4[hid * 8 + ti] = w;
        }
        __syncthreads();
        if (w8 > 0) {
            const float4 o4 = swsum4[hid * 8 + w8 - 1];
            x.x += o4.x; x.y += o4.y; x.z += o4.z; x.w += o4.w;
        }
        spow[tid] = x;
    }
    __syncthreads();

    // Candidate compaction per half: slots k with e_k > TAU * prefix_e[k]
    {
        const bool flag = (se[tid] > TAU * spow[tid].x);
        const unsigned int bal = __ballot_sync(0xffffffffu, flag);
        if (lane == 0) warp_cc[widg] = __popc(bal);
        __syncthreads();
        int off = 0;
        #pragma unroll
        for (int w = 0; w < 8; ++w) off += (w < w8) ? warp_cc[hid * 8 + w] : 0;
        if (flag) {
            const int pos = off + __popc(bal & ((1u << lane) - 1u));
            cand_e[hb + pos] = se[tid];
            cand_k[hb + pos] = ti;
        }
    }
    __syncthreads();
    int Q = 0;
    #pragma unroll
    for (int w = 0; w < 8; ++w) Q += warp_cc[hid * 8 + w];

    // Per-slot compute (thread owns sorted slot ti of its half)
    const float tm_s = stm[hb + ti];
    const float bmax = stm[hb];
    float contrib = 0.0f;
    const bool elim = (tm_s > 0.0f) && (tm_s < bmax);
    if (elim) {
        // cnt = slot+1 + trailing ties (sorted descending, ties contiguous)
        int cnt = ti + 1;
        while (cnt < N_DIM && stm[hb + cnt] == tm_s) ++cnt;

        const float4 S  = spow[hb + cnt - 1];
        const float den = S.x;
        const float id  = __fdividef(1.0f, den);
        const float id2 = id * id;
        float part2 = S.x * id + 0.5f * (S.y * id2)
                    + (1.0f / 3.0f) * (S.z * (id2 * id)) + 0.25f * (S.w * (id2 * id2));
        part2 -= poly_mlog1m(se[hb + ti] * id);   // remove self term exactly

        // Exact-log corrections for the few large-x pairs
        for (int q = 0; q < Q; ++q) {
            const int k = cand_k[hb + q];
            if (k >= cnt) break;                   // list ascending in k
            const float x = cand_e[hb + q] * id;
            if (x > TAU && k != ti) {
                const float ex = -__logf(fmaxf(1.0f + EPS_F - x, 2.0f * EPS_F));
                contrib += ex - poly_mlog1m(x);
            }
        }
        const float w = fminf(fmaxf((bmax - tm_s) / fmaxf(bmax, 1.0f), 0.0f), 1.0f);
        contrib = (__logf(den) - sp[hb + ti] + part2 + contrib) * w;
    }

    // Per-half reduce -> g_tf[row]
    #pragma unroll
    for (int o = 16; o > 0; o >>= 1)
        contrib += __shfl_xor_sync(0xffffffffu, contrib, o);
    if (lane == 0) sredA[widg] = contrib;
    __syncthreads();
    if (ti == 0) {
        float s = 0.0f;
        #pragma unroll
        for (int k = 0; k < 8; ++k) s += sredA[hid * 8 + k];
        const float flag = (stm[hb + 1] >= 0.0f) ? 1.0f : 0.0f;   // >=2 valid
        g_tf[row] = make_float2(s * flag, flag);
    }
    __syncthreads();
    if (tid == 0) {
        __threadfence();
        const unsigned int tk = atomicAdd(&g_ticket, 1u);
        s_islast = (tk == gridDim.x - 1) ? 1 : 0;
    }
    __syncthreads();

    // Last finishing block: deterministic final reduction (fixed order)
    if (s_islast) {
        if (tid == 0) g_ticket = 0;   // reset for next graph replay
        __threadfence();
        float T = 0.0f, F = 0.0f;
        if (tid < B_DIM) {
            const float2 tf = g_tf[tid];
            T = tf.x; F = tf.y;
        }
        #pragma unroll
        for (int o = 16; o > 0; o >>= 1) {
            T += __shfl_xor_sync(0xffffffffu, T, o);
            F += __shfl_xor_sync(0xffffffffu, F, o);
        }
        if (lane == 0) { sredA[widg] = T; sredB[widg] = F; }
        __syncthreads();
        if (tid == 0) {
            float TT = 0.0f, FF = 0.0f;
            #pragma unroll
            for (int k = 0; k < 16; ++k) { TT += sredA[k]; FF += sredB[k]; }
            out[0] = TT / fmaxf(FF, 1.0f);
        }
    }
}

extern "C" void kernel_launch(void* const* d_in, const int* in_sizes, int n_in,
                              void* d_out, int out_size) {
    (void)in_sizes; (void)n_in; (void)out_size;
    const float*        pred   = (const float*)d_in[0];
    const float*        target = (const float*)d_in[1];
    const unsigned int* mask   = (const unsigned int*)d_in[2];

    cox_kernel<<<B_DIM / 2, 512>>>(pred, target, mask, (float*)d_out);
}

// round 7
// speedup vs baseline: 1.5643x; 1.1696x over previous
#include <cuda_runtime.h>

#define B_DIM 256
#define N_DIM 256
#define EPS_F 1e-7f
#define TAU   0.1f

// Scratch (no allocations allowed anywhere)
__device__ float2       g_tf[B_DIM];
__device__ unsigned int g_ticket;

__device__ __forceinline__ float poly_mlog1m(float x) {
    // Sum_{m=1..4} x^m/m  (approximates -log(1-x))
    return x * fmaf(x, fmaf(x, fmaf(x, 0.25f, 1.0f / 3.0f), 0.5f), 1.0f);
}

// -----------------------------------------------------------------------------
// One block per batch row. Scatter-free / global-scan-free formulation:
//  * warp bitonic sort of keys (ordered tm bits << 32 | index) -> 8 runs
//  * per-run IN-REGISTER suffix scan of (e, e^2, e^3, e^4) over sorted order
//    -> 33-entry suffix tables in shared (sentinel 0 at [32])
//  * den4_i = sum over runs of suffix_w[count_less_w(u_i)], where the search
//    compares only the 32-bit tm key -> all exact tm-ties are included in the
//    suffix, matching the reference's (T_j >= T_i) semantics exactly
//  * part2 = 4-term log series on den4 - self term + exact-log corrections for
//    candidates (e_k > TAU*den_k superset; den_i >= den_k for k in risk(i))
//  * bmax from lane 31 of each sorted run; last block does final reduction
// -----------------------------------------------------------------------------
__global__ void __launch_bounds__(N_DIM) cox_kernel(
    const float* __restrict__ pred,
    const float* __restrict__ target,
    const unsigned int* __restrict__ mask,
    float* __restrict__ out)
{
    const int b = blockIdx.x;
    const int i = threadIdx.x;
    const int base = b * N_DIM;
    const int lane = i & 31, w8 = i >> 5;

    __shared__ float        a_e[N_DIM];      // e by original index
    __shared__ unsigned int skey32[N_DIM];   // sorted tm-keys (8 runs of 32)
    __shared__ float4       srun[8 * 33];    // per-run suffix sums + sentinel
    __shared__ float        s_runmax[8];     // per-run max tm
    __shared__ float2       candTE[N_DIM];   // candidate (tm, e)
    __shared__ int          candI[N_DIM];    // candidate original index
    __shared__ int          warp_cc[8];
    __shared__ float        sredA[8], sredB[8];
    __shared__ int          s_islast;

    // Loads (mask elements are 4-byte; !=0 covers int and float encodings)
    const float p  = pred[base + i];
    const float t  = target[base + i];
    const bool  v  = mask[base + i] != 0u;

    const float tm = v ? t : -1.0f;
    const float e  = __expf(p);
    a_e[i] = e;

    // Order-preserving key: invalid (-1) sorts below any valid tm >= 0
    const unsigned int fb = __float_as_uint(tm);
    const unsigned int u  = fb ^ ((fb & 0x80000000u) ? 0xFFFFFFFFu : 0x80000000u);
    unsigned long long key = ((unsigned long long)u << 32) | (unsigned int)i;

    const int vcnt = __syncthreads_count(v);   // barrier; publishes a_e

    // Warp bitonic sort, ascending across lanes (15 compare-exchange stages)
    #pragma unroll
    for (int k = 2; k <= 32; k <<= 1) {
        #pragma unroll
        for (int j = k >> 1; j > 0; j >>= 1) {
            const unsigned long long other = __shfl_xor_sync(0xffffffffu, key, j);
            const bool keepmin = (((lane & j) == 0) == ((lane & k) == 0));
            const bool gt = key > other;
            key = (gt == keepmin) ? other : key;
        }
    }

    // Per-run suffix scan (in registers) of sorted (e, e^2, e^3, e^4)
    {
        const unsigned int sidx = (unsigned int)key & 0xFFu;   // original index
        const float es = a_e[sidx];
        const float e2 = es * es;
        float4 x = make_float4(es, e2, e2 * es, e2 * e2);
        #pragma unroll
        for (int o = 1; o < 32; o <<= 1) {
            const float t0 = __shfl_down_sync(0xffffffffu, x.x, o);
            const float t1 = __shfl_down_sync(0xffffffffu, x.y, o);
            const float t2 = __shfl_down_sync(0xffffffffu, x.z, o);
            const float t3 = __shfl_down_sync(0xffffffffu, x.w, o);
            if (lane < 32 - o) { x.x += t0; x.y += t1; x.z += t2; x.w += t3; }
        }
        skey32[i] = (unsigned int)(key >> 32);
        srun[w8 * 33 + lane] = x;
        if (lane == 31) {
            srun[w8 * 33 + 32] = make_float4(0.f, 0.f, 0.f, 0.f);
            const unsigned int uu = (unsigned int)(key >> 32);   // run max key
            const unsigned int fb2 = (uu & 0x80000000u) ? (uu ^ 0x80000000u) : ~uu;
            s_runmax[w8] = __uint_as_float(fb2);
        }
    }
    __syncthreads();

    // den4 = sum over runs of suffix at count_less(u): all tm_j >= tm_i
    float4 den4 = make_float4(0.f, 0.f, 0.f, 0.f);
    #pragma unroll
    for (int w = 0; w < 8; ++w) {
        const int rb = w * 32;
        int lo = 0;
        #pragma unroll
        for (int s = 16; s; s >>= 1)
            if (skey32[rb + lo + s - 1] < u) lo += s;
        lo += (int)(skey32[rb + lo] < u);   // resolve 31 vs 32
        const float4 S = srun[w * 33 + lo];
        den4.x += S.x; den4.y += S.y; den4.z += S.z; den4.w += S.w;
    }
    const float den = den4.x;

    float bmax = s_runmax[0];
    #pragma unroll
    for (int w = 1; w < 8; ++w) bmax = fmaxf(bmax, s_runmax[w]);

    // Candidate compaction: threads with tm>0 and e > TAU*den (own den = den_k)
    {
        const bool flag = (tm > 0.0f) && (e > TAU * den);
        const unsigned int bal = __ballot_sync(0xffffffffu, flag);
        if (lane == 0) warp_cc[w8] = __popc(bal);
        __syncthreads();
        int off = 0;
        #pragma unroll
        for (int w = 0; w < 8; ++w) off += (w < w8) ? warp_cc[w] : 0;
        if (flag) {
            const int pos = off + __popc(bal & ((1u << lane) - 1u));
            candTE[pos] = make_float2(tm, e);
            candI[pos]  = i;
        }
    }
    __syncthreads();
    int Q = 0;
    #pragma unroll
    for (int w = 0; w < 8; ++w) Q += warp_cc[w];

    // Contribution
    float contrib = 0.0f;
    const bool elim = (tm > 0.0f) && (tm < bmax);
    if (elim) {
        const float id  = __fdividef(1.0f, den);
        const float id2 = id * id;
        float part2 = den4.x * id + 0.5f * (den4.y * id2)
                    + (1.0f / 3.0f) * (den4.z * (id2 * id)) + 0.25f * (den4.w * (id2 * id2));
        part2 -= poly_mlog1m(e * id);   // remove self term exactly

        // Exact-log corrections for pairs in risk(i) with x > TAU
        for (int q = 0; q < Q; ++q) {
            const float2 te = candTE[q];
            const float x = te.y * id;
            if (te.x >= tm && x > TAU && candI[q] != i) {
                contrib += -__logf(fmaxf(1.0f + EPS_F - x, 2.0f * EPS_F)) - poly_mlog1m(x);
            }
        }
        const float w = fminf(fmaxf((bmax - tm) / fmaxf(bmax, 1.0f), 0.0f), 1.0f);
        contrib = (__logf(den) - p + part2 + contrib) * w;
    }

    // Block reduce -> g_tf[b]
    #pragma unroll
    for (int o = 16; o > 0; o >>= 1)
        contrib += __shfl_xor_sync(0xffffffffu, contrib, o);
    if (lane == 0) sredA[w8] = contrib;
    __syncthreads();
    if (i == 0) {
        float s = 0.0f;
        #pragma unroll
        for (int k = 0; k < 8; ++k) s += sredA[k];
        const float flag = (vcnt >= 2) ? 1.0f : 0.0f;
        g_tf[b] = make_float2(s * flag, flag);
        __threadfence();
        const unsigned int tk = atomicAdd(&g_ticket, 1u);
        s_islast = (tk == gridDim.x - 1) ? 1 : 0;
    }
    __syncthreads();

    // Last finishing block: deterministic final reduction (fixed order)
    if (s_islast) {
        if (i == 0) g_ticket = 0;   // reset for next graph replay
        __threadfence();
        const float2 tf = g_tf[i];
        float T = tf.x, F = tf.y;
        #pragma unroll
        for (int o = 16; o > 0; o >>= 1) {
            T += __shfl_xor_sync(0xffffffffu, T, o);
            F += __shfl_xor_sync(0xffffffffu, F, o);
        }
        if (lane == 0) { sredA[w8] = T; sredB[w8] = F; }
        __syncthreads();
        if (i == 0) {
            float TT = 0.0f, FF = 0.0f;
            #pragma unroll
            for (int k = 0; k < 8; ++k) { TT += sredA[k]; FF += sredB[k]; }
            out[0] = TT / fmaxf(FF, 1.0f);
        }
    }
}

extern "C" void kernel_launch(void* const* d_in, const int* in_sizes, int n_in,
                              void* d_out, int out_size) {
    (void)in_sizes; (void)n_in; (void)out_size;
    const float*        pred   = (const float*)d_in[0];
    const float*        target = (const float*)d_in[1];
    const unsigned int* mask   = (const unsigned int*)d_in[2];

    cox_kernel<<<B_DIM, N_DIM>>>(pred, target, mask, (float*)d_out);
}

// round 8
// speedup vs baseline: 1.5923x; 1.0179x over previous
#include <cuda_runtime.h>

#define B_DIM 256
#define N_DIM 256
#define EPS_F 1e-7f
#define TAU   0.1f

// Scratch (no allocations allowed anywhere)
__device__ float2       g_tf[B_DIM];
__device__ unsigned int g_ticket;

__device__ __forceinline__ float poly_mlog1m(float x) {
    // Sum_{m=1..4} x^m/m  (approximates -log(1-x))
    return x * fmaf(x, fmaf(x, fmaf(x, 0.25f, 1.0f / 3.0f), 0.5f), 1.0f);
}

// -----------------------------------------------------------------------------
// One block per batch row. Warp-local sort + suffix tables (round 7), minus
// every removable barrier / staging array:
//  * bitonic sort is warp-local -> payload e recovered post-sort with one
//    variable-lane shfl (key low bits = original index); no shared staging,
//    no initial barrier
//  * per-warp candidate regions (no cross-warp offset scan, one less barrier)
//  * warp-0 ticket + warp-local deterministic final reduction (no broadcast
//    barrier, no last-block internal barriers)
// Barriers: 3 total.
// -----------------------------------------------------------------------------
__global__ void __launch_bounds__(N_DIM) cox_kernel(
    const float* __restrict__ pred,
    const float* __restrict__ target,
    const unsigned int* __restrict__ mask,
    float* __restrict__ out)
{
    const int b = blockIdx.x;
    const int i = threadIdx.x;
    const int base = b * N_DIM;
    const int lane = i & 31, w8 = i >> 5;

    __shared__ unsigned int skey32[N_DIM];   // sorted tm-keys (8 runs of 32)
    __shared__ float4       srun[8 * 33];    // per-run suffix sums + sentinel
    __shared__ float        s_runmax[8];     // per-run max tm
    __shared__ float2       candTE[N_DIM];   // per-warp candidate regions
    __shared__ int          candI[N_DIM];
    __shared__ int          warp_cc[8];
    __shared__ int          warp_vc[8];
    __shared__ float        sredA[8];

    // Loads (mask elements are 4-byte; !=0 covers int and float encodings)
    const float p  = pred[base + i];
    const float t  = target[base + i];
    const bool  v  = mask[base + i] != 0u;

    const float tm = v ? t : -1.0f;
    const float e  = __expf(p);

    // Per-warp valid count (read only after bar3)
    {
        const unsigned int bv = __ballot_sync(0xffffffffu, v);
        if (lane == 0) warp_vc[w8] = __popc(bv);
    }

    // Order-preserving key (invalid -1 sorts below valid tm >= 0), index low
    const unsigned int fb = __float_as_uint(tm);
    const unsigned int u  = fb ^ ((fb & 0x80000000u) ? 0xFFFFFFFFu : 0x80000000u);
    unsigned long long key = ((unsigned long long)u << 32) | (unsigned int)i;

    // Warp bitonic sort, ascending across lanes (15 compare-exchange stages)
    #pragma unroll
    for (int k = 2; k <= 32; k <<= 1) {
        #pragma unroll
        for (int j = k >> 1; j > 0; j >>= 1) {
            const unsigned long long other = __shfl_xor_sync(0xffffffffu, key, j);
            const bool keepmin = (((lane & j) == 0) == ((lane & k) == 0));
            const bool gt = key > other;
            key = (gt == keepmin) ? other : key;
        }
    }

    // Payload fetch: sorted element's original index stays inside this warp
    const float es = __shfl_sync(0xffffffffu, e, (int)key & 31);

    // Per-run in-register suffix scan of (e, e^2, e^3, e^4)
    {
        const float e2 = es * es;
        float4 x = make_float4(es, e2, e2 * es, e2 * e2);
        #pragma unroll
        for (int o = 1; o < 32; o <<= 1) {
            const float t0 = __shfl_down_sync(0xffffffffu, x.x, o);
            const float t1 = __shfl_down_sync(0xffffffffu, x.y, o);
            const float t2 = __shfl_down_sync(0xffffffffu, x.z, o);
            const float t3 = __shfl_down_sync(0xffffffffu, x.w, o);
            if (lane < 32 - o) { x.x += t0; x.y += t1; x.z += t2; x.w += t3; }
        }
        skey32[i] = (unsigned int)(key >> 32);
        srun[w8 * 33 + lane] = x;
        if (lane == 31) {
            srun[w8 * 33 + 32] = make_float4(0.f, 0.f, 0.f, 0.f);
            const unsigned int uu  = (unsigned int)(key >> 32);   // run max key
            const unsigned int fb2 = (uu & 0x80000000u) ? (uu ^ 0x80000000u) : ~uu;
            s_runmax[w8] = __uint_as_float(fb2);
        }
    }
    __syncthreads();                                   // bar1

    // den4 = sum over runs of suffix at count_less(u): all tm_j >= tm_i
    float4 den4 = make_float4(0.f, 0.f, 0.f, 0.f);
    #pragma unroll
    for (int w = 0; w < 8; ++w) {
        const int rb = w * 32;
        int lo = 0;
        #pragma unroll
        for (int s = 16; s; s >>= 1)
            if (skey32[rb + lo + s - 1] < u) lo += s;
        lo += (int)(skey32[rb + lo] < u);              // resolve 31 vs 32
        const float4 S = srun[w * 33 + lo];
        den4.x += S.x; den4.y += S.y; den4.z += S.z; den4.w += S.w;
    }
    const float den = den4.x;

    float bmax = s_runmax[0];
    #pragma unroll
    for (int w = 1; w < 8; ++w) bmax = fmaxf(bmax, s_runmax[w]);

    // Candidates (x > TAU superset: den_i >= den_k for k in risk(i)), per-warp
    {
        const bool flag = (tm > 0.0f) && (e > TAU * den);
        const unsigned int bal = __ballot_sync(0xffffffffu, flag);
        if (lane == 0) warp_cc[w8] = __popc(bal);
        if (flag) {
            const int pos = __popc(bal & ((1u << lane) - 1u));
            candTE[w8 * 32 + pos] = make_float2(tm, e);
            candI [w8 * 32 + pos] = i;
        }
    }
    __syncthreads();                                   // bar2

    // Contribution
    float contrib = 0.0f;
    const bool elim = (tm > 0.0f) && (tm < bmax);
    if (elim) {
        const float id  = __fdividef(1.0f, den);
        const float id2 = id * id;
        float part2 = den4.x * id + 0.5f * (den4.y * id2)
                    + (1.0f / 3.0f) * (den4.z * (id2 * id)) + 0.25f * (den4.w * (id2 * id2));
        part2 -= poly_mlog1m(e * id);                  // remove self term exactly

        // Exact-log corrections (per-warp lists; almost always empty)
        #pragma unroll
        for (int w = 0; w < 8; ++w) {
            const int nw = warp_cc[w];
            for (int q = 0; q < nw; ++q) {
                const float2 te = candTE[w * 32 + q];
                const float x = te.y * id;
                if (te.x >= tm && x > TAU && candI[w * 32 + q] != i)
                    contrib += -__logf(fmaxf(1.0f + EPS_F - x, 2.0f * EPS_F)) - poly_mlog1m(x);
            }
        }
        const float w = fminf(fmaxf((bmax - tm) / fmaxf(bmax, 1.0f), 0.0f), 1.0f);
        contrib = (__logf(den) - p + part2 + contrib) * w;
    }

    // Block reduce -> g_tf[b]
    #pragma unroll
    for (int o = 16; o > 0; o >>= 1)
        contrib += __shfl_xor_sync(0xffffffffu, contrib, o);
    if (lane == 0) sredA[w8] = contrib;
    __syncthreads();                                   // bar3

    // Warp 0 finishes: publish row result; last ticket-holder reduces all rows
    if (w8 == 0) {
        unsigned int tk = 0;
        if (lane == 0) {
            float s = 0.0f;
            int vcnt = 0;
            #pragma unroll
            for (int k = 0; k < 8; ++k) { s += sredA[k]; vcnt += warp_vc[k]; }
            const float flagv = (vcnt >= 2) ? 1.0f : 0.0f;
            g_tf[b] = make_float2(s * flagv, flagv);
            __threadfence();
            tk = atomicAdd(&g_ticket, 1u);
        }
        tk = __shfl_sync(0xffffffffu, tk, 0);
        if (tk == (unsigned int)gridDim.x - 1u) {      // last block's warp 0
            if (lane == 0) g_ticket = 0;               // reset for next replay
            __threadfence();
            float T = 0.0f, F = 0.0f;
            #pragma unroll
            for (int k = 0; k < 8; ++k) {              // fixed order: deterministic
                const float2 tf = g_tf[lane * 8 + k];
                T += tf.x; F += tf.y;
            }
            #pragma unroll
            for (int o = 16; o > 0; o >>= 1) {
                T += __shfl_xor_sync(0xffffffffu, T, o);
                F += __shfl_xor_sync(0xffffffffu, F, o);
            }
            if (lane == 0) out[0] = T / fmaxf(F, 1.0f);
        }
    }
}

extern "C" void kernel_launch(void* const* d_in, const int* in_sizes, int n_in,
                              void* d_out, int out_size) {
    (void)in_sizes; (void)n_in; (void)out_size;
    const float*        pred   = (const float*)d_in[0];
    const float*        target = (const float*)d_in[1];
    const unsigned int* mask   = (const unsigned int*)d_in[2];

    cox_kernel<<<B_DIM, N_DIM>>>(pred, target, mask, (float*)d_out);
}